// round 12
// baseline (speedup 1.0000x reference)
#include <cuda_runtime.h>
#include <cuda_fp16.h>

// V=100000, K=32, F=64.
// out[v, 0:64]   = mean over K neighbours of x[idxs[v,k], :]
// out[v, 64:128] = max  over K neighbours
//
// Two kernels + PDL (R9 structure).
// R12 gather coding: FOUR vertices per warp, QUARTER-warp per gathered row.
//   lane = 8*g + p: vertex v = 4*warp + g, lane loads int4 (16B) at chunk p
//   of each of v's gathered rows -> one LDG.128 gathers 4 rows (4 lines per
//   request). Amortizes SHFL/addr/store overhead over 4 vertices:
//   ~9.5M instrs vs R11's 14.5M, LDG count 0.8M (frontier test: R6 1-line
//   33.1us, R11 2-line 27.6us, this is the 4-line point with the clean
//   shuffle-free epilogue).

#define KNN  32
#define FDIM 64
#define VMAX 100000

__device__ __align__(16) __half2 g_xh[VMAX * (FDIM / 2)];   // 12.8 MB

__global__ __launch_bounds__(256)
void convert_kernel(const float4* __restrict__ x4, int n8)   // n8 = V*F/8
{
    int i = blockIdx.x * blockDim.x + threadIdx.x;
    if (i < n8) {
        float4 a = x4[2 * i];
        float4 b = x4[2 * i + 1];
        __half2 h0 = __floats2half2_rn(a.x, a.y);
        __half2 h1 = __floats2half2_rn(a.z, a.w);
        __half2 h2 = __floats2half2_rn(b.x, b.y);
        __half2 h3 = __floats2half2_rn(b.z, b.w);
        int4 packed;
        packed.x = *(const int*)&h0;
        packed.y = *(const int*)&h1;
        packed.z = *(const int*)&h2;
        packed.w = *(const int*)&h3;
        *reinterpret_cast<int4*>(&g_xh[4 * i]) = packed;
    }
    asm volatile("griddepcontrol.launch_dependents;" ::: "memory");
}

__device__ __forceinline__ void stg_cs_f4(float4* p, float4 v)
{
    asm volatile("st.global.cs.v4.f32 [%0], {%1,%2,%3,%4};"
                 :: "l"(p), "f"(v.x), "f"(v.y), "f"(v.z), "f"(v.w)
                 : "memory");
}

__global__ __launch_bounds__(256, 6)   // ~42-reg budget (12 h2 accumulators)
void knn_mean_max_kernel(const int4* __restrict__ idx4,
                         float4*     __restrict__ out4,
                         int V)
{
    const int warp = (blockIdx.x * blockDim.x + threadIdx.x) >> 5;
    const int lane = threadIdx.x & 31;
    const int g    = lane >> 3;        // which vertex of the quad
    const int p    = lane & 7;         // 16B-chunk position within the row
    const int v    = 4 * warp + g;     // this quarter-warp's vertex
    const bool active = (v < V);

    // Coalesced idx load: warp covers idxs of its 4 vertices (512B).
    // lane l holds idxs[4w + l/8][(l%8)*4 .. +4).
    int4 ia = make_int4(0, 0, 0, 0);
    if (active) ia = idx4[warp * 32 + lane];

    // Block until convert's g_xh writes are visible.
    asm volatile("griddepcontrol.wait;" ::: "memory");

    if (!active) return;

    const __half2 zero = __float2half2_rn(0.0f);
    const __half2 ninf = __float2half2_rn(-65504.0f);
    __half2 sa0 = zero, sa1 = zero, sa2 = zero, sa3 = zero;  // even-k chains
    __half2 sb0 = zero, sb1 = zero, sb2 = zero, sb3 = zero;  // odd-k chains
    __half2 m0 = ninf, m1 = ninf, m2 = ninf, m3 = ninf;

    // Lane reads int4 chunk p (= half2 4p..4p+3) of each gathered row.
    const int4* __restrict__ xl = reinterpret_cast<const int4*>(g_xh) + p;
    const int srcbase = lane & 24;     // shuffles stay within quarter-warp

    #pragma unroll
    for (int k = 0; k < KNN; ++k) {
        // idxs[v][k]: lane srcbase + k/4, int4 component k&3 (compile-time).
        const int c = k & 3;
        const int src = srcbase + (k >> 2);
        const int idx = __shfl_sync(0xffffffffu,
                                    (c == 0) ? ia.x : (c == 1) ? ia.y
                                             : (c == 2) ? ia.z : ia.w,
                                    src);
        const int4 d = __ldg(xl + (size_t)(unsigned)idx * 8);  // row = 8 int4
        const __half2 h0 = *(const __half2*)&d.x;
        const __half2 h1 = *(const __half2*)&d.y;
        const __half2 h2 = *(const __half2*)&d.z;
        const __half2 h3 = *(const __half2*)&d.w;
        if (k & 1) {
            sb0 = __hadd2(sb0, h0); sb1 = __hadd2(sb1, h1);
            sb2 = __hadd2(sb2, h2); sb3 = __hadd2(sb3, h3);
        } else {
            sa0 = __hadd2(sa0, h0); sa1 = __hadd2(sa1, h1);
            sa2 = __hadd2(sa2, h2); sa3 = __hadd2(sa3, h3);
        }
        m0 = __hmax2(m0, h0); m1 = __hmax2(m1, h1);
        m2 = __hmax2(m2, h2); m3 = __hmax2(m3, h3);
    }

    const float inv = 1.0f / KNN;
    const float2 a0 = __half22float2(sa0), b0 = __half22float2(sb0);
    const float2 a1 = __half22float2(sa1), b1 = __half22float2(sb1);
    const float2 a2 = __half22float2(sa2), b2 = __half22float2(sb2);
    const float2 a3 = __half22float2(sa3), b3 = __half22float2(sb3);
    const float2 x0 = __half22float2(m0),  x1 = __half22float2(m1);
    const float2 x2 = __half22float2(m2),  x3 = __half22float2(m3);

    // Lane p owns features [8p, 8p+8) of vertex v.
    // out row = 128 floats = 32 float4: [mean 16 float4 | max 16 float4].
    float4 mean_lo = make_float4((a0.x + b0.x) * inv, (a0.y + b0.y) * inv,
                                 (a1.x + b1.x) * inv, (a1.y + b1.y) * inv);
    float4 mean_hi = make_float4((a2.x + b2.x) * inv, (a2.y + b2.y) * inv,
                                 (a3.x + b3.x) * inv, (a3.y + b3.y) * inv);
    float4 max_lo  = make_float4(x0.x, x0.y, x1.x, x1.y);
    float4 max_hi  = make_float4(x2.x, x2.y, x3.x, x3.y);

    stg_cs_f4(&out4[v * 32 + 2 * p],          mean_lo);
    stg_cs_f4(&out4[v * 32 + 2 * p + 1],      mean_hi);
    stg_cs_f4(&out4[v * 32 + 16 + 2 * p],     max_lo);
    stg_cs_f4(&out4[v * 32 + 16 + 2 * p + 1], max_hi);
}

extern "C" void kernel_launch(void* const* d_in, const int* in_sizes, int n_in,
                              void* d_out, int out_size)
{
    const float4* x4   = (const float4*)d_in[0];  // x: [V, 64] float32
    const int4*   idx4 = (const int4*)d_in[1];    // idxs: [V, 32] int32
    float4*       out4 = (float4*)d_out;          // out: [V, 128] float32

    const int V  = in_sizes[0] / FDIM;            // 100000
    const int n8 = in_sizes[0] / 8;               // V*F/8 (16B per thread)

    convert_kernel<<<(n8 + 255) / 256, 256>>>(x4, n8);

    const int warps = (V + 3) / 4;                // 4 vertices per warp
    const int blocks = (warps + 7) / 8;           // 8 warps per block

    cudaLaunchConfig_t cfg = {};
    cfg.gridDim  = dim3((unsigned)blocks, 1, 1);
    cfg.blockDim = dim3(256, 1, 1);
    cfg.dynamicSmemBytes = 0;
    cfg.stream = 0;

    cudaLaunchAttribute attrs[1];
    attrs[0].id = cudaLaunchAttributeProgrammaticStreamSerialization;
    attrs[0].val.programmaticStreamSerializationAllowed = 1;
    cfg.attrs = attrs;
    cfg.numAttrs = 1;

    cudaLaunchKernelEx(&cfg, knn_mean_max_kernel, idx4, out4, V);
}

// round 13
// speedup vs baseline: 1.1785x; 1.1785x over previous
#include <cuda_runtime.h>
#include <cuda_fp16.h>

// V=100000, K=32, F=64.
// out[v, 0:64]   = mean over K neighbours of x[idxs[v,k], :]
// out[v, 64:128] = max  over K neighbours
//
// Two kernels + PDL. Gather = R11 layout (2 vertices/warp, half-warp per
// row, LDG.64 per lane -> 2 lines per request = the measured optimum of the
// lines-per-request frontier) + R13 change: explicit 2-deep software
// pipeline (prefetch k+1's SHFL+LDG before accumulating k). R11 was
// latency-exposed (issue 46.5%, 7.8us gap between L1-busy 19.8us and wall
// 27.6us, MLP=1); 2 loads in flight closes the scoreboard-wait windows.
// __launch_bounds__(256,7) gives the 36-reg budget the pipeline needs.

#define KNN  32
#define FDIM 64
#define VMAX 100000

__device__ __align__(16) __half2 g_xh[VMAX * (FDIM / 2)];   // 12.8 MB

__global__ __launch_bounds__(256)
void convert_kernel(const float4* __restrict__ x4, int n8)   // n8 = V*F/8
{
    int i = blockIdx.x * blockDim.x + threadIdx.x;
    if (i < n8) {
        float4 a = x4[2 * i];
        float4 b = x4[2 * i + 1];
        __half2 h0 = __floats2half2_rn(a.x, a.y);
        __half2 h1 = __floats2half2_rn(a.z, a.w);
        __half2 h2 = __floats2half2_rn(b.x, b.y);
        __half2 h3 = __floats2half2_rn(b.z, b.w);
        int4 packed;
        packed.x = *(const int*)&h0;
        packed.y = *(const int*)&h1;
        packed.z = *(const int*)&h2;
        packed.w = *(const int*)&h3;
        *reinterpret_cast<int4*>(&g_xh[4 * i]) = packed;
    }
    asm volatile("griddepcontrol.launch_dependents;" ::: "memory");
}

__device__ __forceinline__ void stg_cs_f4(float4* p, float4 v)
{
    asm volatile("st.global.cs.v4.f32 [%0], {%1,%2,%3,%4};"
                 :: "l"(p), "f"(v.x), "f"(v.y), "f"(v.z), "f"(v.w)
                 : "memory");
}

__device__ __forceinline__ uint2 ldg_nc_u2(const __half2* p)
{
    uint2 d;
    asm("ld.global.nc.v2.u32 {%0,%1}, [%2];" : "=r"(d.x), "=r"(d.y) : "l"(p));
    return d;
}

__global__ __launch_bounds__(256, 7)   // 36-reg budget: room for MLP=2
void knn_mean_max_kernel(const int2* __restrict__ idx2,
                         float4*     __restrict__ out4,
                         int V)
{
    const int warp = (blockIdx.x * blockDim.x + threadIdx.x) >> 5;
    const int lane = threadIdx.x & 31;
    const int h    = lane >> 4;        // which vertex of the pair
    const int hl   = lane & 15;        // position within half-warp
    const int v    = 2 * warp + h;     // this half-warp's vertex
    const bool active = (v < V);

    // Coalesced idx load: lanes 0..31 cover 256B = idxs of both vertices.
    int2 pair = make_int2(0, 0);
    if (active) pair = idx2[v * (KNN / 2) + hl];

    // Block until convert's g_xh writes are visible.
    asm volatile("griddepcontrol.wait;" ::: "memory");

    if (!active) return;

    const __half2 zero = __float2half2_rn(0.0f);
    const __half2 ninf = __float2half2_rn(-65504.0f);
    __half2 sa0 = zero, sa1 = zero, sb0 = zero, sb1 = zero;  // 2x16 chains
    __half2 m0 = ninf, m1 = ninf;

    // Lane reads half2 pair (8B) at offset hl of each gathered row
    // (row = 32 half2 = 128B; 16 lanes * 8B cover it).
    const __half2* __restrict__ xl = g_xh + 2 * hl;
    const int srcbase = lane & 16;     // shuffles stay within the half-warp

    // ---- software pipeline, depth 2: prefetch k+1 before consuming k ----
    int idx0 = __shfl_sync(0xffffffffu, pair.x, srcbase);
    uint2 d = ldg_nc_u2(xl + (size_t)(unsigned)idx0 * (FDIM / 2));

    #pragma unroll
    for (int k = 0; k < KNN; ++k) {
        uint2 dn;
        if (k < KNN - 1) {
            const int kn = k + 1;
            const int idxn = __shfl_sync(0xffffffffu,
                                         (kn & 1) ? pair.y : pair.x,
                                         srcbase + (kn >> 1));
            dn = ldg_nc_u2(xl + (size_t)(unsigned)idxn * (FDIM / 2));
        }
        const __half2 ha = *(const __half2*)&d.x;
        const __half2 hb = *(const __half2*)&d.y;
        if (k & 1) { sb0 = __hadd2(sb0, ha); sb1 = __hadd2(sb1, hb); }
        else       { sa0 = __hadd2(sa0, ha); sa1 = __hadd2(sa1, hb); }
        m0 = __hmax2(m0, ha);
        m1 = __hmax2(m1, hb);
        if (k < KNN - 1) d = dn;
    }

    const float2 f0a = __half22float2(sa0), f0b = __half22float2(sb0);
    const float2 f1a = __half22float2(sa1), f1b = __half22float2(sb1);
    const float2 fm0 = __half22float2(m0),  fm1 = __half22float2(m1);
    const float inv = 1.0f / KNN;

    // Lane holds features [4*hl, 4*hl+4) of vertex v.
    // out row = 128 floats = 32 float4: [mean 16 float4 | max 16 float4].
    float4 mean = make_float4((f0a.x + f0b.x) * inv, (f0a.y + f0b.y) * inv,
                              (f1a.x + f1b.x) * inv, (f1a.y + f1b.y) * inv);
    float4 mx   = make_float4(fm0.x, fm0.y, fm1.x, fm1.y);

    stg_cs_f4(&out4[v * 32 + hl],      mean);
    stg_cs_f4(&out4[v * 32 + 16 + hl], mx);
}

extern "C" void kernel_launch(void* const* d_in, const int* in_sizes, int n_in,
                              void* d_out, int out_size)
{
    const float4* x4   = (const float4*)d_in[0];  // x: [V, 64] float32
    const int2*   idx2 = (const int2*)d_in[1];    // idxs: [V, 32] int32
    float4*       out4 = (float4*)d_out;          // out: [V, 128] float32

    const int V  = in_sizes[0] / FDIM;            // 100000
    const int n8 = in_sizes[0] / 8;               // V*F/8 (16B per thread)

    convert_kernel<<<(n8 + 255) / 256, 256>>>(x4, n8);

    const int warps = (V + 1) / 2;                // 2 vertices per warp
    const int blocks = (warps + 7) / 8;           // 8 warps per block

    cudaLaunchConfig_t cfg = {};
    cfg.gridDim  = dim3((unsigned)blocks, 1, 1);
    cfg.blockDim = dim3(256, 1, 1);
    cfg.dynamicSmemBytes = 0;
    cfg.stream = 0;

    cudaLaunchAttribute attrs[1];
    attrs[0].id = cudaLaunchAttributeProgrammaticStreamSerialization;
    attrs[0].val.programmaticStreamSerializationAllowed = 1;
    cfg.attrs = attrs;
    cfg.numAttrs = 1;

    cudaLaunchKernelEx(&cfg, knn_mean_max_kernel, idx2, out4, V);
}